// round 14
// baseline (speedup 1.0000x reference)
#include <cuda_runtime.h>
#include <cuda_fp16.h>
#include <math.h>
#include <stdint.h>

#define NPTS 16384
#define DIM 64
#define MB 128
#define NB 128
#define NSPLIT 16
#define NITER ((NPTS / NB) / NSPLIT)   // 8 n-blocks per CTA

__device__ float g_xsq[NPTS];
__device__ float g_pfsq[NPTS];
__device__ int   g_dmin[NPTS];
__device__ __half g_xh[NPTS * DIM];   // x rounded to fp16
__device__ __half g_ah[NPTS * DIM];   // -2*pf rounded to fp16

#define SWZ(x) ((x) ^ (((x) >> 3) & 0x70))

__device__ __forceinline__ uint32_t smem_u32(const void* p) {
    uint32_t a;
    asm("{ .reg .u64 t; cvta.to.shared.u64 t, %1; cvt.u32.u64 %0, t; }" : "=r"(a) : "l"(p));
    return a;
}

#define LDSM4(d, addr)                                                          \
    asm volatile("ldmatrix.sync.aligned.m8n8.x4.shared.b16 {%0,%1,%2,%3}, [%4];"\
        : "=r"((d)[0]), "=r"((d)[1]), "=r"((d)[2]), "=r"((d)[3]) : "r"(addr))

#define MMA16816(c, a, b0, b1)                                                  \
    asm volatile("mma.sync.aligned.m16n8k16.row.col.f32.f16.f16.f32 "           \
        "{%0,%1,%2,%3}, {%4,%5,%6,%7}, {%8,%9}, {%0,%1,%2,%3};"                 \
        : "+f"((c)[0]), "+f"((c)[1]), "+f"((c)[2]), "+f"((c)[3])                \
        : "r"((a)[0]), "r"((a)[1]), "r"((a)[2]), "r"((a)[3]), "r"(b0), "r"(b1))

#define CP_ASYNC16(dst, src)                                                    \
    asm volatile("cp.async.ca.shared.global [%0], [%1], 16;" :: "r"(dst), "l"(src))
#define CP_COMMIT() asm volatile("cp.async.commit_group;" ::: "memory")
#define CP_WAIT(n)  asm volatile("cp.async.wait_group %0;" :: "n"(n) : "memory")

// ---------------- prep: fp16 rounding + norms of the ROUNDED values ----------------
__global__ void prep_kernel(const float* __restrict__ x, const float* __restrict__ pf) {
    int t = blockIdx.x * 256 + threadIdx.x;       // 0 .. 2*NPTS*8-1
    int side = (t >= NPTS * 8);                   // 0 = x, 1 = pf
    int tt = side ? (t - NPTS * 8) : t;
    int row = tt >> 3;
    int chunk = tt & 7;                           // 8 elems per thread
    const float* src = side ? pf : x;
    const float4* p = (const float4*)(src + (size_t)row * DIM + chunk * 8);
    float4 v0 = p[0], v1 = p[1];
    float vals[8] = {v0.x, v0.y, v0.z, v0.w, v1.x, v1.y, v1.z, v1.w};
    float scale = side ? -2.0f : 1.0f;
    unsigned short hb[8];
    float s = 0.f;
#pragma unroll
    for (int i = 0; i < 8; i++) {
        __half h = __float2half_rn(vals[i] * scale);
        hb[i] = __half_as_ushort(h);
        float f = __half2float(h);
        s += f * f;
    }
    if (side) s *= 0.25f;   // ||pf'||^2 from the stored -2*pf'
    s += __shfl_xor_sync(0xffffffffu, s, 1);
    s += __shfl_xor_sync(0xffffffffu, s, 2);
    s += __shfl_xor_sync(0xffffffffu, s, 4);
    uint4 hw;
    hw.x = ((uint32_t)hb[1] << 16) | hb[0];  hw.y = ((uint32_t)hb[3] << 16) | hb[2];
    hw.z = ((uint32_t)hb[5] << 16) | hb[4];  hw.w = ((uint32_t)hb[7] << 16) | hb[6];
    __half* dst = side ? g_ah : g_xh;
    *(uint4*)(dst + (size_t)row * DIM + chunk * 8) = hw;
    if (chunk == 0) {
        if (side) { g_pfsq[row] = s; g_dmin[row] = 0x7F7FFFFF; }
        else      { g_xsq[row] = s; }
    }
}

// ---------------- main: HMMA GEMM + fused row-min, xs-preloaded accumulators ----------------
// smem: A 16KB | B 2x16KB | xs 2x512B
#define SM_A 0
#define SM_B 16384
#define SM_XS 49152
#define SM_TOTAL (49152 + 1024)

__global__ __launch_bounds__(256, 2) void igd_hmma() {
    extern __shared__ char smem[];
    const uint32_t sb = smem_u32(smem);
    const int tid = threadIdx.x;
    const int lane = tid & 31;
    const int wid = tid >> 5;
    const int warp_m = wid & 3;    // 4 warps along m: 32 rows each
    const int warp_n = wid >> 2;   // 2 warps along n: 64 cols each
    const int m0 = blockIdx.y * MB;

    // GMEM<->SMEM tile mapping: row = tid&127, FOUR uint4 chunks starting at j0.
    const int trow = tid & 127;
    const int j0 = (tid >> 7) * 4;

    // ---- load A tile (-2*pf), swizzled ----
    {
        const uint4* pa = (const uint4*)(g_ah + (size_t)(m0 + trow) * DIM);
#pragma unroll
        for (int j = 0; j < 4; j++) {
            uint4 a = pa[j0 + j];
            *(uint4*)(smem + SM_A + SWZ((uint32_t)(trow * 128 + (j0 + j) * 16))) = a;
        }
    }

    // ---- prologue: cp.async stage 0 of B + xs ----
    {
        const int n0 = blockIdx.x * NB;
        const char* src = (const char*)(g_xh + (size_t)(n0 + trow) * DIM);
        uint32_t db = sb + SM_B;
#pragma unroll
        for (int j = 0; j < 4; j++)
            CP_ASYNC16(db + SWZ((uint32_t)(trow * 128 + (j0 + j) * 16)), src + (j0 + j) * 16);
        if (tid < 32)
            CP_ASYNC16(sb + SM_XS + tid * 16, (const char*)(g_xsq + n0) + tid * 16);
        CP_COMMIT();
    }
    __syncthreads();   // A tile visible

    // ---- extract A fragments, held in registers for the whole CTA lifetime ----
    uint32_t af[2][4][4];   // [m-tile][k-step][regs] = 32 regs
    {
        const int ra = warp_m * 32 + (lane & 15);
        const int kb = (lane >> 4) * 8;
#pragma unroll
        for (int mt = 0; mt < 2; mt++)
#pragma unroll
            for (int ks = 0; ks < 4; ks++) {
                uint32_t addr = sb + SM_A + SWZ((uint32_t)((ra + mt * 16) * 128 + (ks * 16 + kb) * 2));
                LDSM4(af[mt][ks], addr);
            }
    }

    const int g = lane >> 3;
    const int rbb = warp_n * 64 + (g & 1) * 8 + (lane & 7);
    const int kbb = (g >> 1) * 8;

    float rmin[4] = {3.0e38f, 3.0e38f, 3.0e38f, 3.0e38f};

    for (int it = 0; it < NITER; it++) {
        const int p = it & 1;
        __syncthreads();   // prior compute's reads of stage 1-p are done
        if (it + 1 < NITER) {
            const int n0n = (blockIdx.x + NSPLIT * (it + 1)) * NB;
            const char* src = (const char*)(g_xh + (size_t)(n0n + trow) * DIM);
            uint32_t db = sb + SM_B + (1 - p) * 16384;
#pragma unroll
            for (int j = 0; j < 4; j++)
                CP_ASYNC16(db + SWZ((uint32_t)(trow * 128 + (j0 + j) * 16)), src + (j0 + j) * 16);
            if (tid < 32)
                CP_ASYNC16(sb + SM_XS + (1 - p) * 512 + tid * 16,
                           (const char*)(g_xsq + n0n) + tid * 16);
            CP_COMMIT();
            CP_WAIT(1);    // oldest group (stage p) complete
        } else {
            CP_WAIT(0);
        }
        __syncthreads();   // stage p visible to all warps

        const uint32_t sbB = sb + SM_B + p * 16384;
        const float* xs_s = (const float*)(smem + SM_XS + p * 512);

        // accumulators initialized with ||x_n||^2 -> MMA chain yields xs + (-2 pf.x) directly
        float acc[2][8][4];
#pragma unroll
        for (int nt = 0; nt < 8; nt++) {
            float2 xv = *(const float2*)&xs_s[warp_n * 64 + nt * 8 + (lane & 3) * 2];
#pragma unroll
            for (int mt = 0; mt < 2; mt++) {
                acc[mt][nt][0] = xv.x;  acc[mt][nt][1] = xv.y;
                acc[mt][nt][2] = xv.x;  acc[mt][nt][3] = xv.y;
            }
        }

#pragma unroll
        for (int ks = 0; ks < 4; ks++) {
#pragma unroll
            for (int nc = 0; nc < 4; nc++) {
                uint32_t bf[4];
                uint32_t addr = sbB +
                    SWZ((uint32_t)((rbb + nc * 16) * 128 + (ks * 16 + kbb) * 2));
                LDSM4(bf, addr);
#pragma unroll
                for (int mt = 0; mt < 2; mt++) {
                    MMA16816(acc[mt][nc * 2 + 0], af[mt][ks], bf[0], bf[2]);
                    MMA16816(acc[mt][nc * 2 + 1], af[mt][ks], bf[1], bf[3]);
                }
            }
        }

        // fused epilogue: pure running min (xs already inside acc)
#pragma unroll
        for (int nt = 0; nt < 8; nt++) {
#pragma unroll
            for (int mt = 0; mt < 2; mt++) {
                rmin[mt * 2 + 0] = fminf(rmin[mt * 2 + 0],
                    fminf(acc[mt][nt][0], acc[mt][nt][1]));
                rmin[mt * 2 + 1] = fminf(rmin[mt * 2 + 1],
                    fminf(acc[mt][nt][2], acc[mt][nt][3]));
            }
        }
    }

    // reduce the 4 column-lanes of each row group, then one atomic per row
#pragma unroll
    for (int i = 0; i < 4; i++) {
        rmin[i] = fminf(rmin[i], __shfl_xor_sync(0xffffffffu, rmin[i], 1));
        rmin[i] = fminf(rmin[i], __shfl_xor_sync(0xffffffffu, rmin[i], 2));
    }
    if ((lane & 3) == 0) {
#pragma unroll
        for (int mt = 0; mt < 2; mt++)
#pragma unroll
            for (int rg = 0; rg < 2; rg++) {
                int row = m0 + warp_m * 32 + mt * 16 + rg * 8 + (lane >> 2);
                float v = fmaxf(rmin[mt * 2 + rg] + g_pfsq[row], 0.0f);
                atomicMin(&g_dmin[row], __float_as_int(v));  // v >= 0: int order == float order
            }
    }
}

// ---------------- final reduce ----------------
__global__ void finish_kernel(float* __restrict__ out) {
    __shared__ float red[1024];
    int tid = threadIdx.x;
    float s = 0.f;
    for (int m = tid; m < NPTS; m += 1024)
        s += sqrtf(__int_as_float(g_dmin[m]));
    red[tid] = s;
    __syncthreads();
    for (int off = 512; off > 0; off >>= 1) {
        if (tid < off) red[tid] += red[tid + off];
        __syncthreads();
    }
    if (tid == 0) out[0] = red[0] / (float)NPTS;
}

extern "C" void kernel_launch(void* const* d_in, const int* in_sizes, int n_in,
                              void* d_out, int out_size) {
    const float* x  = (const float*)d_in[0];   // [16384, 64]
    const float* pf = (const float*)d_in[1];   // [16384, 64]
    float* out = (float*)d_out;

    cudaFuncSetAttribute(igd_hmma, cudaFuncAttributeMaxDynamicSharedMemorySize, SM_TOTAL);

    prep_kernel<<<(2 * NPTS * 8) / 256, 256>>>(x, pf);
    igd_hmma<<<dim3(NSPLIT, NPTS / MB), 256, SM_TOTAL>>>();
    finish_kernel<<<1, 1024>>>(out);
}

// round 16
// speedup vs baseline: 1.0843x; 1.0843x over previous
#include <cuda_runtime.h>
#include <cuda_fp16.h>
#include <math.h>
#include <stdint.h>

#define NPTS 16384
#define DIM 64
#define MB 128
#define NB 128
#define NSPLIT 16
#define NITER ((NPTS / NB) / NSPLIT)   // 8 n-blocks per CTA

__device__ float g_xsq[NPTS];
__device__ float g_pfsq[NPTS];
__device__ int   g_dmin[NPTS];
__device__ __half g_xh[NPTS * DIM];   // x rounded to fp16
__device__ __half g_ah[NPTS * DIM];   // -2*pf rounded to fp16

#define SWZ(x) ((x) ^ (((x) >> 3) & 0x70))

__device__ __forceinline__ uint32_t smem_u32(const void* p) {
    uint32_t a;
    asm("{ .reg .u64 t; cvta.to.shared.u64 t, %1; cvt.u32.u64 %0, t; }" : "=r"(a) : "l"(p));
    return a;
}

#define LDSM4(d, addr)                                                          \
    asm volatile("ldmatrix.sync.aligned.m8n8.x4.shared.b16 {%0,%1,%2,%3}, [%4];"\
        : "=r"((d)[0]), "=r"((d)[1]), "=r"((d)[2]), "=r"((d)[3]) : "r"(addr))

#define MMA16816(c, a, b0, b1)                                                  \
    asm volatile("mma.sync.aligned.m16n8k16.row.col.f32.f16.f16.f32 "           \
        "{%0,%1,%2,%3}, {%4,%5,%6,%7}, {%8,%9}, {%0,%1,%2,%3};"                 \
        : "+f"((c)[0]), "+f"((c)[1]), "+f"((c)[2]), "+f"((c)[3])                \
        : "r"((a)[0]), "r"((a)[1]), "r"((a)[2]), "r"((a)[3]), "r"(b0), "r"(b1))

// first-k variant: C = 0 (RZ), acc is output-only -> no explicit zero-init MOVs
#define MMA16816_Z(c, a, b0, b1)                                                \
    asm volatile("mma.sync.aligned.m16n8k16.row.col.f32.f16.f16.f32 "           \
        "{%0,%1,%2,%3}, {%4,%5,%6,%7}, {%8,%9}, {%10,%10,%10,%10};"             \
        : "=f"((c)[0]), "=f"((c)[1]), "=f"((c)[2]), "=f"((c)[3])                \
        : "r"((a)[0]), "r"((a)[1]), "r"((a)[2]), "r"((a)[3]), "r"(b0), "r"(b1), \
          "f"(0.0f))

#define CP_ASYNC16(dst, src)                                                    \
    asm volatile("cp.async.ca.shared.global [%0], [%1], 16;" :: "r"(dst), "l"(src))
#define CP_COMMIT() asm volatile("cp.async.commit_group;" ::: "memory")
#define CP_WAIT(n)  asm volatile("cp.async.wait_group %0;" :: "n"(n) : "memory")

// ---------------- prep: fp16 rounding + norms of the ROUNDED values ----------------
__global__ void prep_kernel(const float* __restrict__ x, const float* __restrict__ pf) {
    int t = blockIdx.x * 256 + threadIdx.x;       // 0 .. 2*NPTS*8-1
    int side = (t >= NPTS * 8);                   // 0 = x, 1 = pf
    int tt = side ? (t - NPTS * 8) : t;
    int row = tt >> 3;
    int chunk = tt & 7;                           // 8 elems per thread
    const float* src = side ? pf : x;
    const float4* p = (const float4*)(src + (size_t)row * DIM + chunk * 8);
    float4 v0 = p[0], v1 = p[1];
    float vals[8] = {v0.x, v0.y, v0.z, v0.w, v1.x, v1.y, v1.z, v1.w};
    float scale = side ? -2.0f : 1.0f;
    unsigned short hb[8];
    float s = 0.f;
#pragma unroll
    for (int i = 0; i < 8; i++) {
        __half h = __float2half_rn(vals[i] * scale);
        hb[i] = __half_as_ushort(h);
        float f = __half2float(h);
        s += f * f;
    }
    if (side) s *= 0.25f;   // ||pf'||^2 from the stored -2*pf'
    s += __shfl_xor_sync(0xffffffffu, s, 1);
    s += __shfl_xor_sync(0xffffffffu, s, 2);
    s += __shfl_xor_sync(0xffffffffu, s, 4);
    uint4 hw;
    hw.x = ((uint32_t)hb[1] << 16) | hb[0];  hw.y = ((uint32_t)hb[3] << 16) | hb[2];
    hw.z = ((uint32_t)hb[5] << 16) | hb[4];  hw.w = ((uint32_t)hb[7] << 16) | hb[6];
    __half* dst = side ? g_ah : g_xh;
    *(uint4*)(dst + (size_t)row * DIM + chunk * 8) = hw;
    if (chunk == 0) {
        if (side) { g_pfsq[row] = s; g_dmin[row] = 0x7F7FFFFF; }
        else      { g_xsq[row] = s; }
    }
}

// ---------------- main: HMMA GEMM + fused row-min, MMA-zero-init, occ 2 ----------------
// smem: A 16KB | B 2x16KB | xs 2x512B
#define SM_A 0
#define SM_B 16384
#define SM_XS 49152
#define SM_TOTAL (49152 + 1024)

__global__ __launch_bounds__(256, 2) void igd_hmma() {
    extern __shared__ char smem[];
    const uint32_t sb = smem_u32(smem);
    const int tid = threadIdx.x;
    const int lane = tid & 31;
    const int wid = tid >> 5;
    const int warp_m = wid & 3;    // 4 warps along m: 32 rows each
    const int warp_n = wid >> 2;   // 2 warps along n: 64 cols each
    const int m0 = blockIdx.y * MB;

    // GMEM<->SMEM tile mapping: row = tid&127, FOUR uint4 chunks starting at j0.
    const int trow = tid & 127;
    const int j0 = (tid >> 7) * 4;

    // ---- load A tile (-2*pf), swizzled ----
    {
        const uint4* pa = (const uint4*)(g_ah + (size_t)(m0 + trow) * DIM);
#pragma unroll
        for (int j = 0; j < 4; j++) {
            uint4 a = pa[j0 + j];
            *(uint4*)(smem + SM_A + SWZ((uint32_t)(trow * 128 + (j0 + j) * 16))) = a;
        }
    }

    // ---- prologue: cp.async stage 0 of B + xs ----
    {
        const int n0 = blockIdx.x * NB;
        const char* src = (const char*)(g_xh + (size_t)(n0 + trow) * DIM);
        uint32_t db = sb + SM_B;
#pragma unroll
        for (int j = 0; j < 4; j++)
            CP_ASYNC16(db + SWZ((uint32_t)(trow * 128 + (j0 + j) * 16)), src + (j0 + j) * 16);
        if (tid < 32)
            CP_ASYNC16(sb + SM_XS + tid * 16, (const char*)(g_xsq + n0) + tid * 16);
        CP_COMMIT();
    }
    __syncthreads();   // A tile visible

    // ---- extract A fragments, held in registers for the whole CTA lifetime ----
    uint32_t af[2][4][4];   // [m-tile][k-step][regs] = 32 regs
    {
        const int ra = warp_m * 32 + (lane & 15);
        const int kb = (lane >> 4) * 8;
#pragma unroll
        for (int mt = 0; mt < 2; mt++)
#pragma unroll
            for (int ks = 0; ks < 4; ks++) {
                uint32_t addr = sb + SM_A + SWZ((uint32_t)((ra + mt * 16) * 128 + (ks * 16 + kb) * 2));
                LDSM4(af[mt][ks], addr);
            }
    }

    const int g = lane >> 3;
    const int rbb = warp_n * 64 + (g & 1) * 8 + (lane & 7);
    const int kbb = (g >> 1) * 8;

    float rmin[4] = {3.0e38f, 3.0e38f, 3.0e38f, 3.0e38f};

    for (int it = 0; it < NITER; it++) {
        const int p = it & 1;
        __syncthreads();   // prior compute's reads of stage 1-p are done
        if (it + 1 < NITER) {
            const int n0n = (blockIdx.x + NSPLIT * (it + 1)) * NB;
            const char* src = (const char*)(g_xh + (size_t)(n0n + trow) * DIM);
            uint32_t db = sb + SM_B + (1 - p) * 16384;
#pragma unroll
            for (int j = 0; j < 4; j++)
                CP_ASYNC16(db + SWZ((uint32_t)(trow * 128 + (j0 + j) * 16)), src + (j0 + j) * 16);
            if (tid < 32)
                CP_ASYNC16(sb + SM_XS + (1 - p) * 512 + tid * 16,
                           (const char*)(g_xsq + n0n) + tid * 16);
            CP_COMMIT();
            CP_WAIT(1);    // oldest group (stage p) complete
        } else {
            CP_WAIT(0);
        }
        __syncthreads();   // stage p visible to all warps

        const uint32_t sbB = sb + SM_B + p * 16384;
        const float* xs_s = (const float*)(smem + SM_XS + p * 512);

        // full-width accumulators; first ks-step writes them via C=0 MMA (no init MOVs)
        float acc[2][8][4];

#pragma unroll
        for (int ks = 0; ks < 4; ks++) {
#pragma unroll
            for (int nc = 0; nc < 4; nc++) {
                uint32_t bf[4];
                uint32_t addr = sbB +
                    SWZ((uint32_t)((rbb + nc * 16) * 128 + (ks * 16 + kbb) * 2));
                LDSM4(bf, addr);
#pragma unroll
                for (int mt = 0; mt < 2; mt++) {
                    if (ks == 0) {
                        MMA16816_Z(acc[mt][nc * 2 + 0], af[mt][0], bf[0], bf[2]);
                        MMA16816_Z(acc[mt][nc * 2 + 1], af[mt][0], bf[1], bf[3]);
                    } else {
                        MMA16816(acc[mt][nc * 2 + 0], af[mt][ks], bf[0], bf[2]);
                        MMA16816(acc[mt][nc * 2 + 1], af[mt][ks], bf[1], bf[3]);
                    }
                }
            }
        }

        // fused epilogue: running min over this n-block of (acc + xs[col])
#pragma unroll
        for (int nt = 0; nt < 8; nt++) {
            float2 xv = *(const float2*)&xs_s[warp_n * 64 + nt * 8 + (lane & 3) * 2];
#pragma unroll
            for (int mt = 0; mt < 2; mt++) {
                rmin[mt * 2 + 0] = fminf(rmin[mt * 2 + 0],
                    fminf(acc[mt][nt][0] + xv.x, acc[mt][nt][1] + xv.y));
                rmin[mt * 2 + 1] = fminf(rmin[mt * 2 + 1],
                    fminf(acc[mt][nt][2] + xv.x, acc[mt][nt][3] + xv.y));
            }
        }
    }

    // reduce the 4 column-lanes of each row group, then one atomic per row
#pragma unroll
    for (int i = 0; i < 4; i++) {
        rmin[i] = fminf(rmin[i], __shfl_xor_sync(0xffffffffu, rmin[i], 1));
        rmin[i] = fminf(rmin[i], __shfl_xor_sync(0xffffffffu, rmin[i], 2));
    }
    if ((lane & 3) == 0) {
#pragma unroll
        for (int mt = 0; mt < 2; mt++)
#pragma unroll
            for (int rg = 0; rg < 2; rg++) {
                int row = m0 + warp_m * 32 + mt * 16 + rg * 8 + (lane >> 2);
                float v = fmaxf(rmin[mt * 2 + rg] + g_pfsq[row], 0.0f);
                atomicMin(&g_dmin[row], __float_as_int(v));  // v >= 0: int order == float order
            }
    }
}

// ---------------- final reduce ----------------
__global__ void finish_kernel(float* __restrict__ out) {
    __shared__ float red[1024];
    int tid = threadIdx.x;
    float s = 0.f;
    for (int m = tid; m < NPTS; m += 1024)
        s += sqrtf(__int_as_float(g_dmin[m]));
    red[tid] = s;
    __syncthreads();
    for (int off = 512; off > 0; off >>= 1) {
        if (tid < off) red[tid] += red[tid + off];
        __syncthreads();
    }
    if (tid == 0) out[0] = red[0] / (float)NPTS;
}

extern "C" void kernel_launch(void* const* d_in, const int* in_sizes, int n_in,
                              void* d_out, int out_size) {
    const float* x  = (const float*)d_in[0];   // [16384, 64]
    const float* pf = (const float*)d_in[1];   // [16384, 64]
    float* out = (float*)d_out;

    cudaFuncSetAttribute(igd_hmma, cudaFuncAttributeMaxDynamicSharedMemorySize, SM_TOTAL);

    prep_kernel<<<(2 * NPTS * 8) / 256, 256>>>(x, pf);
    igd_hmma<<<dim3(NSPLIT, NPTS / MB), 256, SM_TOTAL>>>();
    finish_kernel<<<1, 1024>>>(out);
}

// round 17
// speedup vs baseline: 1.0997x; 1.0142x over previous
#include <cuda_runtime.h>
#include <cuda_fp16.h>
#include <math.h>
#include <stdint.h>

#define NPTS 16384
#define DIM 64
#define MB 128
#define NB 128
#define NSPLIT 16
#define NITER ((NPTS / NB) / NSPLIT)   // 8 n-blocks per CTA

__device__ float g_xsq[NPTS];
__device__ float g_pfsq[NPTS];
__device__ int   g_dmin[NPTS];
__device__ __half g_xh[NPTS * DIM];   // x rounded to fp16
__device__ __half g_ah[NPTS * DIM];   // -2*pf rounded to fp16

#define SWZ(x) ((x) ^ (((x) >> 3) & 0x70))

__device__ __forceinline__ uint32_t smem_u32(const void* p) {
    uint32_t a;
    asm("{ .reg .u64 t; cvta.to.shared.u64 t, %1; cvt.u32.u64 %0, t; }" : "=r"(a) : "l"(p));
    return a;
}

#define LDSM4(d, addr)                                                          \
    asm volatile("ldmatrix.sync.aligned.m8n8.x4.shared.b16 {%0,%1,%2,%3}, [%4];"\
        : "=r"((d)[0]), "=r"((d)[1]), "=r"((d)[2]), "=r"((d)[3]) : "r"(addr))

#define MMA16816(c, a, b0, b1)                                                  \
    asm volatile("mma.sync.aligned.m16n8k16.row.col.f32.f16.f16.f32 "           \
        "{%0,%1,%2,%3}, {%4,%5,%6,%7}, {%8,%9}, {%0,%1,%2,%3};"                 \
        : "+f"((c)[0]), "+f"((c)[1]), "+f"((c)[2]), "+f"((c)[3])                \
        : "r"((a)[0]), "r"((a)[1]), "r"((a)[2]), "r"((a)[3]), "r"(b0), "r"(b1))

// first-k variant: C = 0 (RZ), acc is output-only -> no explicit zero-init MOVs
#define MMA16816_Z(c, a, b0, b1)                                                \
    asm volatile("mma.sync.aligned.m16n8k16.row.col.f32.f16.f16.f32 "           \
        "{%0,%1,%2,%3}, {%4,%5,%6,%7}, {%8,%9}, {%10,%10,%10,%10};"             \
        : "=f"((c)[0]), "=f"((c)[1]), "=f"((c)[2]), "=f"((c)[3])                \
        : "r"((a)[0]), "r"((a)[1]), "r"((a)[2]), "r"((a)[3]), "r"(b0), "r"(b1), \
          "f"(0.0f))

#define CP_ASYNC16(dst, src)                                                    \
    asm volatile("cp.async.ca.shared.global [%0], [%1], 16;" :: "r"(dst), "l"(src))
#define CP_COMMIT() asm volatile("cp.async.commit_group;" ::: "memory")
#define CP_WAIT(n)  asm volatile("cp.async.wait_group %0;" :: "n"(n) : "memory")

// ---------------- prep: fp16 rounding + norms of the ROUNDED values ----------------
__global__ void prep_kernel(const float* __restrict__ x, const float* __restrict__ pf) {
    int t = blockIdx.x * 256 + threadIdx.x;       // 0 .. 2*NPTS*8-1
    int side = (t >= NPTS * 8);                   // 0 = x, 1 = pf
    int tt = side ? (t - NPTS * 8) : t;
    int row = tt >> 3;
    int chunk = tt & 7;                           // 8 elems per thread
    const float* src = side ? pf : x;
    const float4* p = (const float4*)(src + (size_t)row * DIM + chunk * 8);
    float4 v0 = p[0], v1 = p[1];
    float vals[8] = {v0.x, v0.y, v0.z, v0.w, v1.x, v1.y, v1.z, v1.w};
    float scale = side ? -2.0f : 1.0f;
    unsigned short hb[8];
    float s = 0.f;
#pragma unroll
    for (int i = 0; i < 8; i++) {
        __half h = __float2half_rn(vals[i] * scale);
        hb[i] = __half_as_ushort(h);
        float f = __half2float(h);
        s += f * f;
    }
    if (side) s *= 0.25f;   // ||pf'||^2 from the stored -2*pf'
    s += __shfl_xor_sync(0xffffffffu, s, 1);
    s += __shfl_xor_sync(0xffffffffu, s, 2);
    s += __shfl_xor_sync(0xffffffffu, s, 4);
    uint4 hw;
    hw.x = ((uint32_t)hb[1] << 16) | hb[0];  hw.y = ((uint32_t)hb[3] << 16) | hb[2];
    hw.z = ((uint32_t)hb[5] << 16) | hb[4];  hw.w = ((uint32_t)hb[7] << 16) | hb[6];
    __half* dst = side ? g_ah : g_xh;
    *(uint4*)(dst + (size_t)row * DIM + chunk * 8) = hw;
    if (chunk == 0) {
        if (side) { g_pfsq[row] = s; g_dmin[row] = 0x7F7FFFFF; }
        else      { g_xsq[row] = s; }
    }
}

// ---------------- main: HMMA GEMM + fused row-min, 3-stage ring, 1 barrier/iter ----------------
// smem: A 16KB | B 3x16KB | xs 3x512B
#define SM_A 0
#define SM_B 16384
#define SM_XS (16384 + 49152)
#define SM_TOTAL (SM_XS + 3 * 512)

__global__ __launch_bounds__(256, 2) void igd_hmma() {
    extern __shared__ char smem[];
    const uint32_t sb = smem_u32(smem);
    const int tid = threadIdx.x;
    const int lane = tid & 31;
    const int wid = tid >> 5;
    const int warp_m = wid & 3;    // 4 warps along m: 32 rows each
    const int warp_n = wid >> 2;   // 2 warps along n: 64 cols each
    const int m0 = blockIdx.y * MB;

    // GMEM<->SMEM tile mapping: row = tid&127, FOUR uint4 chunks starting at j0.
    const int trow = tid & 127;
    const int j0 = (tid >> 7) * 4;

    // ---- load A tile (-2*pf), swizzled ----
    {
        const uint4* pa = (const uint4*)(g_ah + (size_t)(m0 + trow) * DIM);
#pragma unroll
        for (int j = 0; j < 4; j++) {
            uint4 a = pa[j0 + j];
            *(uint4*)(smem + SM_A + SWZ((uint32_t)(trow * 128 + (j0 + j) * 16))) = a;
        }
    }

    // ---- prologue: cp.async stage 0 of B + xs ----
    {
        const int n0 = blockIdx.x * NB;
        const char* src = (const char*)(g_xh + (size_t)(n0 + trow) * DIM);
        uint32_t db = sb + SM_B;
#pragma unroll
        for (int j = 0; j < 4; j++)
            CP_ASYNC16(db + SWZ((uint32_t)(trow * 128 + (j0 + j) * 16)), src + (j0 + j) * 16);
        if (tid < 32)
            CP_ASYNC16(sb + SM_XS + tid * 16, (const char*)(g_xsq + n0) + tid * 16);
        CP_COMMIT();
    }
    __syncthreads();   // A tile visible

    // ---- extract A fragments, held in registers for the whole CTA lifetime ----
    uint32_t af[2][4][4];   // [m-tile][k-step][regs] = 32 regs
    {
        const int ra = warp_m * 32 + (lane & 15);
        const int kb = (lane >> 4) * 8;
#pragma unroll
        for (int mt = 0; mt < 2; mt++)
#pragma unroll
            for (int ks = 0; ks < 4; ks++) {
                uint32_t addr = sb + SM_A + SWZ((uint32_t)((ra + mt * 16) * 128 + (ks * 16 + kb) * 2));
                LDSM4(af[mt][ks], addr);
            }
    }

    const int g = lane >> 3;
    const int rbb = warp_n * 64 + (g & 1) * 8 + (lane & 7);
    const int kbb = (g >> 1) * 8;

    float rmin[4] = {3.0e38f, 3.0e38f, 3.0e38f, 3.0e38f};

    int ps = 0;   // current read stage (it % 3)
    for (int it = 0; it < NITER; it++) {
        // issue prefetch for stage (it+1)%3: that slot was last read at it-2,
        // and the barrier below (passed by all warps for iter it-1) proves
        // everyone is done with iter it-2's reads.
        if (it + 1 < NITER) {
            const int wslot = (ps == 2) ? 0 : ps + 1;
            const int n0n = (blockIdx.x + NSPLIT * (it + 1)) * NB;
            const char* src = (const char*)(g_xh + (size_t)(n0n + trow) * DIM);
            uint32_t db = sb + SM_B + wslot * 16384;
#pragma unroll
            for (int j = 0; j < 4; j++)
                CP_ASYNC16(db + SWZ((uint32_t)(trow * 128 + (j0 + j) * 16)), src + (j0 + j) * 16);
            if (tid < 32)
                CP_ASYNC16(sb + SM_XS + wslot * 512 + tid * 16,
                           (const char*)(g_xsq + n0n) + tid * 16);
            CP_COMMIT();
            CP_WAIT(1);    // stage ps (committed one iter ago) complete
        } else {
            CP_WAIT(0);
        }
        __syncthreads();   // publishes stage ps to all warps; orders vs slot reuse

        const uint32_t sbB = sb + SM_B + ps * 16384;
        const float* xs_s = (const float*)(smem + SM_XS + ps * 512);

        // full-width accumulators; first ks-step writes them via C=0 MMA (no init MOVs)
        float acc[2][8][4];

#pragma unroll
        for (int ks = 0; ks < 4; ks++) {
#pragma unroll
            for (int nc = 0; nc < 4; nc++) {
                uint32_t bf[4];
                uint32_t addr = sbB +
                    SWZ((uint32_t)((rbb + nc * 16) * 128 + (ks * 16 + kbb) * 2));
                LDSM4(bf, addr);
#pragma unroll
                for (int mt = 0; mt < 2; mt++) {
                    if (ks == 0) {
                        MMA16816_Z(acc[mt][nc * 2 + 0], af[mt][0], bf[0], bf[2]);
                        MMA16816_Z(acc[mt][nc * 2 + 1], af[mt][0], bf[1], bf[3]);
                    } else {
                        MMA16816(acc[mt][nc * 2 + 0], af[mt][ks], bf[0], bf[2]);
                        MMA16816(acc[mt][nc * 2 + 1], af[mt][ks], bf[1], bf[3]);
                    }
                }
            }
        }

        // fused epilogue: running min over this n-block of (acc + xs[col])
#pragma unroll
        for (int nt = 0; nt < 8; nt++) {
            float2 xv = *(const float2*)&xs_s[warp_n * 64 + nt * 8 + (lane & 3) * 2];
#pragma unroll
            for (int mt = 0; mt < 2; mt++) {
                rmin[mt * 2 + 0] = fminf(rmin[mt * 2 + 0],
                    fminf(acc[mt][nt][0] + xv.x, acc[mt][nt][1] + xv.y));
                rmin[mt * 2 + 1] = fminf(rmin[mt * 2 + 1],
                    fminf(acc[mt][nt][2] + xv.x, acc[mt][nt][3] + xv.y));
            }
        }

        ps = (ps == 2) ? 0 : ps + 1;
    }

    // reduce the 4 column-lanes of each row group, then one atomic per row
#pragma unroll
    for (int i = 0; i < 4; i++) {
        rmin[i] = fminf(rmin[i], __shfl_xor_sync(0xffffffffu, rmin[i], 1));
        rmin[i] = fminf(rmin[i], __shfl_xor_sync(0xffffffffu, rmin[i], 2));
    }
    if ((lane & 3) == 0) {
#pragma unroll
        for (int mt = 0; mt < 2; mt++)
#pragma unroll
            for (int rg = 0; rg < 2; rg++) {
                int row = m0 + warp_m * 32 + mt * 16 + rg * 8 + (lane >> 2);
                float v = fmaxf(rmin[mt * 2 + rg] + g_pfsq[row], 0.0f);
                atomicMin(&g_dmin[row], __float_as_int(v));  // v >= 0: int order == float order
            }
    }
}

// ---------------- final reduce ----------------
__global__ void finish_kernel(float* __restrict__ out) {
    __shared__ float red[1024];
    int tid = threadIdx.x;
    float s = 0.f;
    for (int m = tid; m < NPTS; m += 1024)
        s += sqrtf(__int_as_float(g_dmin[m]));
    red[tid] = s;
    __syncthreads();
    for (int off = 512; off > 0; off >>= 1) {
        if (tid < off) red[tid] += red[tid + off];
        __syncthreads();
    }
    if (tid == 0) out[0] = red[0] / (float)NPTS;
}

extern "C" void kernel_launch(void* const* d_in, const int* in_sizes, int n_in,
                              void* d_out, int out_size) {
    const float* x  = (const float*)d_in[0];   // [16384, 64]
    const float* pf = (const float*)d_in[1];   // [16384, 64]
    float* out = (float*)d_out;

    cudaFuncSetAttribute(igd_hmma, cudaFuncAttributeMaxDynamicSharedMemorySize, SM_TOTAL);

    prep_kernel<<<(2 * NPTS * 8) / 256, 256>>>(x, pf);
    igd_hmma<<<dim3(NSPLIT, NPTS / MB), 256, SM_TOTAL>>>();
    finish_kernel<<<1, 1024>>>(out);
}